// round 4
// baseline (speedup 1.0000x reference)
#include <cuda_runtime.h>
#include <math.h>

#define BB 16
#define NN 1024
#define MM 1024
#define DD 512
#define NEGV (-2e20f)
#define NCHUNK 16

// ---- scratch (static device memory; no allocations) ----
__device__ float g_S[(size_t)BB * NN * MM];     // 64 MB: masked logits
__device__ float g_q2c[(size_t)BB * MM * DD];   // 32 MB
__device__ float g_s1[BB * NN];
__device__ float g_s2[BB * MM];
__device__ float g_rowM[BB * NN];
__device__ float g_rowIL[BB * NN];
__device__ float g_colM[BB * MM];
__device__ float g_colIL[BB * MM];
__device__ float g_pM[BB * NCHUNK * MM];
__device__ float g_pL[BB * NCHUNK * MM];

// ---------------------------------------------------------------------------
// K0: s1[b,n] = x1[b,n,:] . w[0:512];  s2[b,m] = x2[b,m,:] . w[512:1024]
// one warp per row
// ---------------------------------------------------------------------------
__global__ __launch_bounds__(256) void k_proj(const float* __restrict__ x1,
                                              const float* __restrict__ x2,
                                              const float* __restrict__ w)
{
    int warp = threadIdx.x >> 5, lane = threadIdx.x & 31;
    int row = blockIdx.x * 8 + warp;           // 0 .. 2*BB*NN-1
    const float* x; const float* wv; float* o; int r;
    if (row < BB * NN) { x = x1; wv = w;      o = g_s1; r = row; }
    else               { x = x2; wv = w + DD; o = g_s2; r = row - BB * NN; }
    const float* xr = x + (size_t)r * DD;
    float acc = 0.f;
    #pragma unroll 4
    for (int i = lane; i < DD; i += 32) acc += xr[i] * wv[i];
    #pragma unroll
    for (int s = 16; s; s >>= 1) acc += __shfl_xor_sync(0xffffffffu, acc, s);
    if (lane == 0) o[r] = acc;
}

// ---------------------------------------------------------------------------
// K1: S[b,n,m] = (x1*w3) @ x2^T + s1[n] + s2[m] + bias ; x2_mask -> NEG
// NT gemm, 64x64 tile, BK=16, 256 threads, 4x4 per thread
// ---------------------------------------------------------------------------
__global__ __launch_bounds__(256) void k_sim(const float* __restrict__ x1,
                                             const float* __restrict__ x2,
                                             const float* __restrict__ w,
                                             const float* __restrict__ bias,
                                             const int* __restrict__ x2_mask)
{
    __shared__ float As[16][68];
    __shared__ float Bs[16][68];
    const int b    = blockIdx.z;
    const int row0 = blockIdx.y * 64;          // n
    const int col0 = blockIdx.x * 64;          // m
    const float* Ag = x1 + ((size_t)b * NN + row0) * DD;
    const float* Bg = x2 + ((size_t)b * MM + col0) * DD;
    const float* w3 = w + 2 * DD;
    const int t  = threadIdx.x;
    const int lr = t >> 2;                     // 0..63
    const int lc = (t & 3) * 4;                // 0..12
    const int ty = t >> 4, tx = t & 15;
    float acc[4][4] = {};
    for (int k0 = 0; k0 < DD; k0 += 16) {
        float4 av = *(const float4*)(Ag + (size_t)lr * DD + k0 + lc);
        float4 bv = *(const float4*)(Bg + (size_t)lr * DD + k0 + lc);
        float4 wv = *(const float4*)(w3 + k0 + lc);
        __syncthreads();
        As[lc + 0][lr] = av.x * wv.x;
        As[lc + 1][lr] = av.y * wv.y;
        As[lc + 2][lr] = av.z * wv.z;
        As[lc + 3][lr] = av.w * wv.w;
        Bs[lc + 0][lr] = bv.x;
        Bs[lc + 1][lr] = bv.y;
        Bs[lc + 2][lr] = bv.z;
        Bs[lc + 3][lr] = bv.w;
        __syncthreads();
        #pragma unroll
        for (int k = 0; k < 16; k++) {
            float4 a  = *(const float4*)&As[k][ty * 4];
            float4 bq = *(const float4*)&Bs[k][tx * 4];
            float ai[4] = {a.x, a.y, a.z, a.w};
            float bj[4] = {bq.x, bq.y, bq.z, bq.w};
            #pragma unroll
            for (int i = 0; i < 4; i++)
                #pragma unroll
                for (int j = 0; j < 4; j++)
                    acc[i][j] += ai[i] * bj[j];
        }
    }
    const float biasv = *bias;
    float s1v[4], s2v[4];
    int mk[4];
    #pragma unroll
    for (int i = 0; i < 4; i++) s1v[i] = g_s1[b * NN + row0 + ty * 4 + i];
    #pragma unroll
    for (int j = 0; j < 4; j++) {
        s2v[j] = g_s2[b * MM + col0 + tx * 4 + j];
        mk[j]  = x2_mask[b * MM + col0 + tx * 4 + j];
    }
    #pragma unroll
    for (int i = 0; i < 4; i++) {
        float4 o;
        float* po = (float*)&o;
        #pragma unroll
        for (int j = 0; j < 4; j++) {
            float v = acc[i][j] + s1v[i] + s2v[j] + biasv;
            po[j] = mk[j] ? NEGV : v;
        }
        *(float4*)&g_S[((size_t)b * NN + row0 + ty * 4 + i) * MM + col0 + tx * 4] = o;
    }
}

// ---------------------------------------------------------------------------
// K2: per-row (over m) max and inv-sum-exp.  one block per (b,n) row
// ---------------------------------------------------------------------------
__global__ __launch_bounds__(256) void k_rowstats()
{
    const int r = blockIdx.x;                  // b*NN + n
    const float* row = g_S + (size_t)r * MM;
    const int t = threadIdx.x;
    __shared__ float sm[256];
    float mx = NEGV;
    #pragma unroll 4
    for (int i = t; i < MM; i += 256) mx = fmaxf(mx, row[i]);
    sm[t] = mx; __syncthreads();
    for (int s = 128; s; s >>= 1) { if (t < s) sm[t] = fmaxf(sm[t], sm[t + s]); __syncthreads(); }
    mx = sm[0]; __syncthreads();
    float l = 0.f;
    #pragma unroll 4
    for (int i = t; i < MM; i += 256) l += __expf(row[i] - mx);
    sm[t] = l; __syncthreads();
    for (int s = 128; s; s >>= 1) { if (t < s) sm[t] += sm[t + s]; __syncthreads(); }
    if (t == 0) { g_rowM[r] = mx; g_rowIL[r] = 1.f / sm[0]; }
}

// ---------------------------------------------------------------------------
// K3: partial column stats over n-chunks (x1_mask applied to rows)
// ---------------------------------------------------------------------------
__global__ __launch_bounds__(256) void k_colpart(const int* __restrict__ x1_mask)
{
    const int b = blockIdx.z;
    const int chunk = blockIdx.y;              // 0..15
    const int m = blockIdx.x * 256 + threadIdx.x;
    const float* Sb = g_S + (size_t)b * NN * MM;
    float mx = NEGV, l = 0.f;
    const int n0 = chunk * (NN / NCHUNK);
    for (int n = n0; n < n0 + NN / NCHUNK; n++) {
        float v = x1_mask[b * NN + n] ? NEGV : Sb[(size_t)n * MM + m];
        float mn = fmaxf(mx, v);
        l = l * __expf(mx - mn) + __expf(v - mn);
        mx = mn;
    }
    g_pM[(b * NCHUNK + chunk) * MM + m] = mx;
    g_pL[(b * NCHUNK + chunk) * MM + m] = l;
}

__global__ __launch_bounds__(256) void k_colcomb()
{
    const int idx = blockIdx.x * 256 + threadIdx.x;   // b*MM + m
    const int b = idx / MM, m = idx % MM;
    float mx = NEGV;
    #pragma unroll
    for (int c = 0; c < NCHUNK; c++) mx = fmaxf(mx, g_pM[(b * NCHUNK + c) * MM + m]);
    float l = 0.f;
    #pragma unroll
    for (int c = 0; c < NCHUNK; c++)
        l += g_pL[(b * NCHUNK + c) * MM + m] * __expf(g_pM[(b * NCHUNK + c) * MM + m] - mx);
    g_colM[idx] = mx;
    g_colIL[idx] = 1.f / l;
}

// ---------------------------------------------------------------------------
// K4/K6: Out[b,n,d] = row_softmax(S) @ Bmat[b,m,d]   (Bmat = x2 or q2c)
// NN gemm over K=m, softmax applied on A-tile load
// ---------------------------------------------------------------------------
__global__ __launch_bounds__(256) void k_pv(const float* __restrict__ Bext,
                                            float* __restrict__ Out, int useQ)
{
    __shared__ float Ps[16][68];
    __shared__ float Bs[16][68];
    const int b    = blockIdx.z;
    const int row0 = blockIdx.y * 64;          // n
    const int col0 = blockIdx.x * 64;          // d
    const float* Sb = g_S + ((size_t)b * NN + row0) * MM;
    const float* Bb = (useQ ? (const float*)g_q2c : Bext) + (size_t)b * MM * DD;
    const int t  = threadIdx.x;
    const int ar = t >> 2, ac = (t & 3) * 4;   // A tile: 64 rows(n) x 16 cols(m)
    const int kr = t >> 4, bc = (t & 15) * 4;  // B tile: 16 rows(m) x 64 cols(d)
    const int ty = t >> 4, tx = t & 15;
    const float rM = g_rowM[b * NN + row0 + ar];
    const float rI = g_rowIL[b * NN + row0 + ar];
    float acc[4][4] = {};
    for (int k0 = 0; k0 < MM; k0 += 16) {
        float4 av = *(const float4*)(Sb + (size_t)ar * MM + k0 + ac);
        float4 bv = *(const float4*)(Bb + (size_t)(k0 + kr) * DD + col0 + bc);
        __syncthreads();
        Ps[ac + 0][ar] = __expf(av.x - rM) * rI;
        Ps[ac + 1][ar] = __expf(av.y - rM) * rI;
        Ps[ac + 2][ar] = __expf(av.z - rM) * rI;
        Ps[ac + 3][ar] = __expf(av.w - rM) * rI;
        *(float4*)&Bs[kr][bc] = bv;
        __syncthreads();
        #pragma unroll
        for (int k = 0; k < 16; k++) {
            float4 a  = *(const float4*)&Ps[k][ty * 4];
            float4 bq = *(const float4*)&Bs[k][tx * 4];
            float ai[4] = {a.x, a.y, a.z, a.w};
            float bj[4] = {bq.x, bq.y, bq.z, bq.w};
            #pragma unroll
            for (int i = 0; i < 4; i++)
                #pragma unroll
                for (int j = 0; j < 4; j++)
                    acc[i][j] += ai[i] * bj[j];
        }
    }
    #pragma unroll
    for (int i = 0; i < 4; i++) {
        float4 o = make_float4(acc[i][0], acc[i][1], acc[i][2], acc[i][3]);
        *(float4*)&Out[((size_t)b * NN + row0 + ty * 4 + i) * DD + col0 + tx * 4] = o;
    }
}

// ---------------------------------------------------------------------------
// K5: q2c[b,m,d] = col_softmax(S)^T @ x1[b,n,d]   (TN gemm over K=n)
// ---------------------------------------------------------------------------
__global__ __launch_bounds__(256) void k_q2c(const float* __restrict__ x1,
                                             const int* __restrict__ x1_mask)
{
    __shared__ float Cs[16][68];               // [k=n][m]
    __shared__ float Bs[16][68];               // [k=n][d]
    const int b     = blockIdx.z;
    const int mrow0 = blockIdx.y * 64;         // m
    const int col0  = blockIdx.x * 64;         // d
    const float* Sb = g_S + (size_t)b * NN * MM;
    const float* Xb = x1 + (size_t)b * NN * DD;
    const int t  = threadIdx.x;
    const int kr = t >> 4, cc = (t & 15) * 4;  // both tiles 16 x 64, natural
    const int ty = t >> 4, tx = t & 15;
    float cM[4], cI[4];
    #pragma unroll
    for (int i = 0; i < 4; i++) {
        cM[i] = g_colM[b * MM + mrow0 + cc + i];
        cI[i] = g_colIL[b * MM + mrow0 + cc + i];
    }
    float acc[4][4] = {};
    for (int k0 = 0; k0 < NN; k0 += 16) {
        const int n = k0 + kr;
        const bool msk = x1_mask[b * NN + n] != 0;
        float4 sv = *(const float4*)(Sb + (size_t)n * MM + mrow0 + cc);
        float4 xv = *(const float4*)(Xb + (size_t)n * DD + col0 + cc);
        __syncthreads();
        {
            float v0 = msk ? NEGV : sv.x;
            float v1 = msk ? NEGV : sv.y;
            float v2 = msk ? NEGV : sv.z;
            float v3 = msk ? NEGV : sv.w;
            Cs[kr][cc + 0] = __expf(v0 - cM[0]) * cI[0];
            Cs[kr][cc + 1] = __expf(v1 - cM[1]) * cI[1];
            Cs[kr][cc + 2] = __expf(v2 - cM[2]) * cI[2];
            Cs[kr][cc + 3] = __expf(v3 - cM[3]) * cI[3];
        }
        *(float4*)&Bs[kr][cc] = xv;
        __syncthreads();
        #pragma unroll
        for (int k = 0; k < 16; k++) {
            float4 a  = *(const float4*)&Cs[k][ty * 4];
            float4 bq = *(const float4*)&Bs[k][tx * 4];
            float ai[4] = {a.x, a.y, a.z, a.w};
            float bj[4] = {bq.x, bq.y, bq.z, bq.w};
            #pragma unroll
            for (int i = 0; i < 4; i++)
                #pragma unroll
                for (int j = 0; j < 4; j++)
                    acc[i][j] += ai[i] * bj[j];
        }
    }
    #pragma unroll
    for (int i = 0; i < 4; i++) {
        float4 o = make_float4(acc[i][0], acc[i][1], acc[i][2], acc[i][3]);
        *(float4*)&g_q2c[((size_t)b * MM + mrow0 + ty * 4 + i) * DD + col0 + tx * 4] = o;
    }
}

// ---------------------------------------------------------------------------
extern "C" void kernel_launch(void* const* d_in, const int* in_sizes, int n_in,
                              void* d_out, int out_size)
{
    const float* x1      = (const float*)d_in[0];
    const int*   x1_mask = (const int*)d_in[1];
    const float* x2      = (const float*)d_in[2];
    const int*   x2_mask = (const int*)d_in[3];
    const float* w       = (const float*)d_in[4];
    const float* bias    = (const float*)d_in[5];
    float*       out     = (float*)d_out;

    k_proj<<<(2 * BB * NN) / 8, 256>>>(x1, x2, w);

    dim3 gs(MM / 64, NN / 64, BB);
    k_sim<<<gs, 256>>>(x1, x2, w, bias, x2_mask);

    k_rowstats<<<BB * NN, 256>>>();
    k_colpart<<<dim3(MM / 256, NCHUNK, BB), 256>>>(x1_mask);
    k_colcomb<<<(BB * MM) / 256, 256>>>();

    dim3 gp(DD / 64, NN / 64, BB);
    k_pv<<<gp, 256>>>(x2, out, 0);                         // attn_a

    dim3 gq(DD / 64, MM / 64, BB);
    k_q2c<<<gq, 256>>>(x1, x1_mask);

    k_pv<<<gp, 256>>>(nullptr, out + (size_t)BB * NN * DD, 1);  // attn_b
}

// round 7
// speedup vs baseline: 1.6947x; 1.6947x over previous
#include <cuda_runtime.h>
#include <cuda_bf16.h>
#include <stdint.h>
#include <math.h>

#define BB 16
#define NN 1024
#define MM 1024
#define DD 512
#define NEGV (-2e20f)
#define NCHUNK 16

// ---- scratch (static device memory; no allocations) ----
__device__ float g_S[(size_t)BB * NN * MM];     // 64 MB masked logits
__device__ float g_q2c[(size_t)BB * MM * DD];   // 32 MB
__device__ float g_s1[BB * NN];
__device__ float g_s2[BB * MM];
__device__ float g_rowM[BB * NN];
__device__ float g_rowIL[BB * NN];
__device__ float g_colM[BB * MM];
__device__ float g_colIL[BB * MM];
__device__ float g_pM[BB * NCHUNK * MM];
__device__ float g_pL[BB * NCHUNK * MM];

// ---------------------------------------------------------------------------
// helpers: SW128 swizzle, ldmatrix, bf16 mma, split-store
// smem tile layout: 128 rows x 128B; row = [hi: 32 bf16 | lo: 32 bf16]
// ---------------------------------------------------------------------------
__device__ __forceinline__ uint32_t swz(uint32_t off) { return off ^ ((off >> 3) & 0x70u); }

__device__ __forceinline__ void ldsm4(uint32_t addr, unsigned &r0, unsigned &r1,
                                      unsigned &r2, unsigned &r3)
{
    asm volatile("ldmatrix.sync.aligned.m8n8.x4.shared.b16 {%0,%1,%2,%3}, [%4];"
                 : "=r"(r0), "=r"(r1), "=r"(r2), "=r"(r3) : "r"(addr));
}

__device__ __forceinline__ void mmab(float* c, const unsigned* a, const unsigned* b)
{
    asm volatile("mma.sync.aligned.m16n8k16.row.col.f32.bf16.bf16.f32 "
                 "{%0,%1,%2,%3},{%4,%5,%6,%7},{%8,%9},{%0,%1,%2,%3};"
                 : "+f"(c[0]), "+f"(c[1]), "+f"(c[2]), "+f"(c[3])
                 : "r"(a[0]), "r"(a[1]), "r"(a[2]), "r"(a[3]), "r"(b[0]), "r"(b[1]));
}

// split 16 consecutive-K floats into bf16 hi/lo and store to smem row
__device__ __forceinline__ void store16(char* sm, int row, int cg, const float* v)
{
    unsigned h[8], l[8];
    #pragma unroll
    for (int i = 0; i < 8; i++) {
        float a = v[2*i], b = v[2*i+1];
        __nv_bfloat162 hb = __floats2bfloat162_rn(a, b);
        float2 hf = __bfloat1622float2(hb);
        __nv_bfloat162 lb = __floats2bfloat162_rn(a - hf.x, b - hf.y);
        h[i] = *(unsigned*)&hb;
        l[i] = *(unsigned*)&lb;
    }
    uint32_t base = (uint32_t)(row * 128 + cg * 2);
    *(uint4*)(sm + swz(base))      = make_uint4(h[0], h[1], h[2], h[3]);
    *(uint4*)(sm + swz(base + 16)) = make_uint4(h[4], h[5], h[6], h[7]);
    *(uint4*)(sm + swz(base + 64)) = make_uint4(l[0], l[1], l[2], l[3]);
    *(uint4*)(sm + swz(base + 80)) = make_uint4(l[4], l[5], l[6], l[7]);
}

// one BK=32 stage of 3-term split MMAs; warp tile 64(m) x 32(n)
__device__ __forceinline__ void mma_stage(uint32_t asu, uint32_t bsu, int wm, int wn,
                                          int lane, float (*acc)[4][4])
{
    #pragma unroll
    for (int kk = 0; kk < 32; kk += 16) {
        unsigned Ah[4][4], Al[4][4], Bh[4][2], Bl[4][2];
        uint32_t co = (uint32_t)((kk + ((lane >> 4) << 3)) * 2);
        #pragma unroll
        for (int im = 0; im < 4; im++) {
            uint32_t row = wm * 64 + im * 16 + (lane & 15);
            ldsm4(asu + swz(row * 128 + co),      Ah[im][0], Ah[im][1], Ah[im][2], Ah[im][3]);
            ldsm4(asu + swz(row * 128 + 64 + co), Al[im][0], Al[im][1], Al[im][2], Al[im][3]);
        }
        uint32_t cb = (uint32_t)((kk + (((lane >> 3) & 1) << 3)) * 2);
        #pragma unroll
        for (int p = 0; p < 2; p++) {
            uint32_t rb = wn * 32 + p * 16 + (lane & 7) + (((lane >> 4) & 1) << 3);
            ldsm4(bsu + swz(rb * 128 + cb),      Bh[2*p][0], Bh[2*p][1], Bh[2*p+1][0], Bh[2*p+1][1]);
            ldsm4(bsu + swz(rb * 128 + 64 + cb), Bl[2*p][0], Bl[2*p][1], Bl[2*p+1][0], Bl[2*p+1][1]);
        }
        #pragma unroll
        for (int im = 0; im < 4; im++)
            #pragma unroll
            for (int in = 0; in < 4; in++) {
                mmab(acc[im][in], Ah[im], Bh[in]);
                mmab(acc[im][in], Ah[im], Bl[in]);
                mmab(acc[im][in], Al[im], Bh[in]);
            }
    }
}

// ---------------------------------------------------------------------------
// K0: s1 / s2 projections (unchanged)
// ---------------------------------------------------------------------------
__global__ __launch_bounds__(256) void k_proj(const float* __restrict__ x1,
                                              const float* __restrict__ x2,
                                              const float* __restrict__ w)
{
    int warp = threadIdx.x >> 5, lane = threadIdx.x & 31;
    int row = blockIdx.x * 8 + warp;
    const float* x; const float* wv; float* o; int r;
    if (row < BB * NN) { x = x1; wv = w;      o = g_s1; r = row; }
    else               { x = x2; wv = w + DD; o = g_s2; r = row - BB * NN; }
    const float* xr = x + (size_t)r * DD;
    float acc = 0.f;
    #pragma unroll 4
    for (int i = lane; i < DD; i += 32) acc += xr[i] * wv[i];
    #pragma unroll
    for (int s = 16; s; s >>= 1) acc += __shfl_xor_sync(0xffffffffu, acc, s);
    if (lane == 0) o[r] = acc;
}

// ---------------------------------------------------------------------------
// K1: S = (x1*w3) @ x2^T + s1 + s2 + bias, x2_mask -> NEG  (tensor cores)
// ---------------------------------------------------------------------------
__global__ __launch_bounds__(256, 1) void k_sim_t(const float* __restrict__ x1,
                                                  const float* __restrict__ x2,
                                                  const float* __restrict__ w,
                                                  const float* __restrict__ bias,
                                                  const int* __restrict__ x2_mask)
{
    __shared__ __align__(128) char As[128 * 128];
    __shared__ __align__(128) char Bs[128 * 128];
    __shared__ float wsm[DD];
    const int b = blockIdx.z, row0 = blockIdx.y * 128, col0 = blockIdx.x * 128;
    const int t = threadIdx.x, lane = t & 31, wid = t >> 5;
    const int wm = wid & 1, wn = wid >> 1;
    for (int i = t; i < DD; i += 256) wsm[i] = w[2 * DD + i];
    const float* Ag = x1 + ((size_t)b * NN + row0) * DD;
    const float* Bg = x2 + ((size_t)b * MM + col0) * DD;
    const int sr = t >> 1, scg = (t & 1) * 16;
    uint32_t asu = (uint32_t)__cvta_generic_to_shared(As);
    uint32_t bsu = (uint32_t)__cvta_generic_to_shared(Bs);
    float va[16], vb[16];
    float acc[4][4][4] = {};
    __syncthreads();                               // wsm ready
    #pragma unroll
    for (int q = 0; q < 4; q++) {
        float4 fa = *(const float4*)(Ag + (size_t)sr * DD + scg + 4 * q);
        float4 fb = *(const float4*)(Bg + (size_t)sr * DD + scg + 4 * q);
        va[4*q] = fa.x; va[4*q+1] = fa.y; va[4*q+2] = fa.z; va[4*q+3] = fa.w;
        vb[4*q] = fb.x; vb[4*q+1] = fb.y; vb[4*q+2] = fb.z; vb[4*q+3] = fb.w;
    }
    #pragma unroll
    for (int j = 0; j < 16; j++) va[j] *= wsm[scg + j];
    store16(As, sr, scg, va);
    store16(Bs, sr, scg, vb);
    __syncthreads();
    const int nstage = DD / 32;
    for (int s = 1; s <= nstage; s++) {
        const int k0 = s * 32;
        const bool more = (s < nstage);
        if (more) {
            #pragma unroll
            for (int q = 0; q < 4; q++) {
                float4 fa = *(const float4*)(Ag + (size_t)sr * DD + k0 + scg + 4 * q);
                float4 fb = *(const float4*)(Bg + (size_t)sr * DD + k0 + scg + 4 * q);
                va[4*q] = fa.x; va[4*q+1] = fa.y; va[4*q+2] = fa.z; va[4*q+3] = fa.w;
                vb[4*q] = fb.x; vb[4*q+1] = fb.y; vb[4*q+2] = fb.z; vb[4*q+3] = fb.w;
            }
            #pragma unroll
            for (int j = 0; j < 16; j++) va[j] *= wsm[k0 + scg + j];
        }
        mma_stage(asu, bsu, wm, wn, lane, acc);
        __syncthreads();
        if (more) { store16(As, sr, scg, va); store16(Bs, sr, scg, vb); }
        __syncthreads();
    }
    const float biasv = *bias;
    #pragma unroll
    for (int im = 0; im < 4; im++) {
        int r = row0 + wm * 64 + im * 16 + (lane >> 2);
        float s1a = g_s1[b * NN + r], s1b = g_s1[b * NN + r + 8];
        #pragma unroll
        for (int in = 0; in < 4; in++) {
            int c = col0 + wn * 32 + in * 8 + 2 * (lane & 3);
            float s2a = g_s2[b * MM + c], s2b = g_s2[b * MM + c + 1];
            int m0 = x2_mask[b * MM + c], m1 = x2_mask[b * MM + c + 1];
            float* acf = acc[im][in];
            float2 o0, o1;
            o0.x = m0 ? NEGV : (acf[0] + s1a + s2a + biasv);
            o0.y = m1 ? NEGV : (acf[1] + s1a + s2b + biasv);
            o1.x = m0 ? NEGV : (acf[2] + s1b + s2a + biasv);
            o1.y = m1 ? NEGV : (acf[3] + s1b + s2b + biasv);
            *(float2*)&g_S[((size_t)b * NN + r) * MM + c]     = o0;
            *(float2*)&g_S[((size_t)b * NN + r + 8) * MM + c] = o1;
        }
    }
}

// ---------------------------------------------------------------------------
// K2: per-row stats (unchanged)
// ---------------------------------------------------------------------------
__global__ __launch_bounds__(256) void k_rowstats()
{
    const int r = blockIdx.x;
    const float* row = g_S + (size_t)r * MM;
    const int t = threadIdx.x;
    __shared__ float sm[256];
    float mx = NEGV;
    #pragma unroll 4
    for (int i = t; i < MM; i += 256) mx = fmaxf(mx, row[i]);
    sm[t] = mx; __syncthreads();
    for (int s = 128; s; s >>= 1) { if (t < s) sm[t] = fmaxf(sm[t], sm[t + s]); __syncthreads(); }
    mx = sm[0]; __syncthreads();
    float l = 0.f;
    #pragma unroll 4
    for (int i = t; i < MM; i += 256) l += __expf(row[i] - mx);
    sm[t] = l; __syncthreads();
    for (int s = 128; s; s >>= 1) { if (t < s) sm[t] += sm[t + s]; __syncthreads(); }
    if (t == 0) { g_rowM[r] = mx; g_rowIL[r] = 1.f / sm[0]; }
}

// ---------------------------------------------------------------------------
// K3: column stats (unchanged)
// ---------------------------------------------------------------------------
__global__ __launch_bounds__(256) void k_colpart(const int* __restrict__ x1_mask)
{
    const int b = blockIdx.z;
    const int chunk = blockIdx.y;
    const int m = blockIdx.x * 256 + threadIdx.x;
    const float* Sb = g_S + (size_t)b * NN * MM;
    float mx = NEGV, l = 0.f;
    const int n0 = chunk * (NN / NCHUNK);
    for (int n = n0; n < n0 + NN / NCHUNK; n++) {
        float v = x1_mask[b * NN + n] ? NEGV : Sb[(size_t)n * MM + m];
        float mn = fmaxf(mx, v);
        l = l * __expf(mx - mn) + __expf(v - mn);
        mx = mn;
    }
    g_pM[(b * NCHUNK + chunk) * MM + m] = mx;
    g_pL[(b * NCHUNK + chunk) * MM + m] = l;
}

__global__ __launch_bounds__(256) void k_colcomb()
{
    const int idx = blockIdx.x * 256 + threadIdx.x;
    const int b = idx / MM, m = idx % MM;
    float mx = NEGV;
    #pragma unroll
    for (int c = 0; c < NCHUNK; c++) mx = fmaxf(mx, g_pM[(b * NCHUNK + c) * MM + m]);
    float l = 0.f;
    #pragma unroll
    for (int c = 0; c < NCHUNK; c++)
        l += g_pL[(b * NCHUNK + c) * MM + m] * __expf(g_pM[(b * NCHUNK + c) * MM + m] - mx);
    g_colM[idx] = mx;
    g_colIL[idx] = 1.f / l;
}

// ---------------------------------------------------------------------------
// K4/K6: Out = row_softmax(S) @ Bmat  (tensor cores, softmax on A-stage)
// ---------------------------------------------------------------------------
__global__ __launch_bounds__(256, 1) void k_pv_t(const float* __restrict__ Bext,
                                                 float* __restrict__ Out, int useQ)
{
    __shared__ __align__(128) char As[128 * 128];
    __shared__ __align__(128) char Bs[128 * 128];
    const int b = blockIdx.z, row0 = blockIdx.y * 128, col0 = blockIdx.x * 128;
    const int t = threadIdx.x, lane = t & 31, wid = t >> 5;
    const int wm = wid & 1, wn = wid >> 1;
    const float* Sb = g_S + ((size_t)b * NN + row0) * MM;
    const float* Bb = (useQ ? (const float*)g_q2c : Bext) + (size_t)b * MM * DD;
    const int sr = t >> 1, scg = (t & 1) * 16;      // A staging: n-row, k-group
    const int sd = t & 127, sseg = (t >> 7) * 16;   // B staging: d-row, k-group
    const float rM = g_rowM[b * NN + row0 + sr];
    const float rI = g_rowIL[b * NN + row0 + sr];
    uint32_t asu = (uint32_t)__cvta_generic_to_shared(As);
    uint32_t bsu = (uint32_t)__cvta_generic_to_shared(Bs);
    float va[16], vb[16];
    float acc[4][4][4] = {};
    #pragma unroll
    for (int q = 0; q < 4; q++) {
        float4 fa = *(const float4*)(Sb + (size_t)sr * MM + scg + 4 * q);
        va[4*q]   = __expf(fa.x - rM) * rI;
        va[4*q+1] = __expf(fa.y - rM) * rI;
        va[4*q+2] = __expf(fa.z - rM) * rI;
        va[4*q+3] = __expf(fa.w - rM) * rI;
    }
    #pragma unroll
    for (int j = 0; j < 16; j++) vb[j] = Bb[(size_t)(sseg + j) * DD + col0 + sd];
    store16(As, sr, scg, va);
    store16(Bs, sd, sseg, vb);
    __syncthreads();
    const int nstage = MM / 32;
    for (int s = 1; s <= nstage; s++) {
        const int k0 = s * 32;
        const bool more = (s < nstage);
        if (more) {
            #pragma unroll
            for (int q = 0; q < 4; q++) {
                float4 fa = *(const float4*)(Sb + (size_t)sr * MM + k0 + scg + 4 * q);
                va[4*q]   = __expf(fa.x - rM) * rI;
                va[4*q+1] = __expf(fa.y - rM) * rI;
                va[4*q+2] = __expf(fa.z - rM) * rI;
                va[4*q+3] = __expf(fa.w - rM) * rI;
            }
            #pragma unroll
            for (int j = 0; j < 16; j++) vb[j] = Bb[(size_t)(k0 + sseg + j) * DD + col0 + sd];
        }
        mma_stage(asu, bsu, wm, wn, lane, acc);
        __syncthreads();
        if (more) { store16(As, sr, scg, va); store16(Bs, sd, sseg, vb); }
        __syncthreads();
    }
    #pragma unroll
    for (int im = 0; im < 4; im++) {
        int r = row0 + wm * 64 + im * 16 + (lane >> 2);
        #pragma unroll
        for (int in = 0; in < 4; in++) {
            int c = col0 + wn * 32 + in * 8 + 2 * (lane & 3);
            float* acf = acc[im][in];
            *(float2*)&Out[((size_t)b * NN + r) * DD + c]     = make_float2(acf[0], acf[1]);
            *(float2*)&Out[((size_t)b * NN + r + 8) * DD + c] = make_float2(acf[2], acf[3]);
        }
    }
}

// ---------------------------------------------------------------------------
// K5: q2c = col_softmax(S)^T @ x1  (tensor cores, softmax+mask on A-stage)
// ---------------------------------------------------------------------------
__global__ __launch_bounds__(256, 1) void k_q2c_t(const float* __restrict__ x1,
                                                  const int* __restrict__ x1_mask)
{
    __shared__ __align__(128) char As[128 * 128];
    __shared__ __align__(128) char Bs[128 * 128];
    const int b = blockIdx.z, row0m = blockIdx.y * 128, col0 = blockIdx.x * 128;
    const int t = threadIdx.x, lane = t & 31, wid = t >> 5;
    const int wm = wid & 1, wn = wid >> 1;
    const float* Sb = g_S + (size_t)b * NN * MM;
    const float* Xb = x1 + (size_t)b * NN * DD;
    const int sm_ = t & 127, sseg = (t >> 7) * 16;  // A: m-row; B: d-row (same index math)
    const float cM = g_colM[b * MM + row0m + sm_];
    const float cI = g_colIL[b * MM + row0m + sm_];
    uint32_t asu = (uint32_t)__cvta_generic_to_shared(As);
    uint32_t bsu = (uint32_t)__cvta_generic_to_shared(Bs);
    float va[16], vb[16];
    float acc[4][4][4] = {};
    #pragma unroll
    for (int j = 0; j < 16; j++) {
        int n = sseg + j;
        float sv = x1_mask[b * NN + n] ? NEGV : Sb[(size_t)n * MM + row0m + sm_];
        va[j] = __expf(sv - cM) * cI;
        vb[j] = Xb[(size_t)n * DD + col0 + sm_];
    }
    store16(As, sm_, sseg, va);
    store16(Bs, sm_, sseg, vb);
    __syncthreads();
    const int nstage = NN / 32;
    for (int s = 1; s <= nstage; s++) {
        const int k0 = s * 32;
        const bool more = (s < nstage);
        if (more) {
            #pragma unroll
            for (int j = 0; j < 16; j++) {
                int n = k0 + sseg + j;
                float sv = x1_mask[b * NN + n] ? NEGV : Sb[(size_t)n * MM + row0m + sm_];
                va[j] = __expf(sv - cM) * cI;
                vb[j] = Xb[(size_t)n * DD + col0 + sm_];
            }
        }
        mma_stage(asu, bsu, wm, wn, lane, acc);
        __syncthreads();
        if (more) { store16(As, sm_, sseg, va); store16(Bs, sm_, sseg, vb); }
        __syncthreads();
    }
    #pragma unroll
    for (int im = 0; im < 4; im++) {
        int r = row0m + wm * 64 + im * 16 + (lane >> 2);
        #pragma unroll
        for (int in = 0; in < 4; in++) {
            int c = col0 + wn * 32 + in * 8 + 2 * (lane & 3);
            float* acf = acc[im][in];
            *(float2*)&g_q2c[((size_t)b * MM + r) * DD + c]     = make_float2(acf[0], acf[1]);
            *(float2*)&g_q2c[((size_t)b * MM + r + 8) * DD + c] = make_float2(acf[2], acf[3]);
        }
    }
}

// ---------------------------------------------------------------------------
extern "C" void kernel_launch(void* const* d_in, const int* in_sizes, int n_in,
                              void* d_out, int out_size)
{
    const float* x1      = (const float*)d_in[0];
    const int*   x1_mask = (const int*)d_in[1];
    const float* x2      = (const float*)d_in[2];
    const int*   x2_mask = (const int*)d_in[3];
    const float* w       = (const float*)d_in[4];
    const float* bias    = (const float*)d_in[5];
    float*       out     = (float*)d_out;

    k_proj<<<(2 * BB * NN) / 8, 256>>>(x1, x2, w);

    dim3 gs(MM / 128, NN / 128, BB);
    k_sim_t<<<gs, 256>>>(x1, x2, w, bias, x2_mask);

    k_rowstats<<<BB * NN, 256>>>();
    k_colpart<<<dim3(MM / 256, NCHUNK, BB), 256>>>(x1_mask);
    k_colcomb<<<(BB * MM) / 256, 256>>>();

    dim3 gp(DD / 128, NN / 128, BB);
    k_pv_t<<<gp, 256>>>(x2, out, 0);                         // attn_a

    dim3 gq(DD / 128, MM / 128, BB);
    k_q2c_t<<<gq, 256>>>(x1, x1_mask);

    k_pv_t<<<gp, 256>>>(nullptr, out + (size_t)BB * NN * DD, 1);  // attn_b
}